// round 1
// baseline (speedup 1.0000x reference)
#include <cuda_runtime.h>
#include <math.h>

// Problem constants
#define Bn  4
#define Ln  1024
#define En  1024
#define Hn  16
#define HDn 64
#define NT  33          // 2*CLIP+1
#define CLIPV 16
#define SCALEF 0.125f   // 1/sqrt(64)

// Scratch (device globals; no allocation allowed)
__device__ float gQ[Bn*Hn*Ln*HDn];   // [b][h][l][d]
__device__ float gK[Bn*Hn*Ln*HDn];
__device__ float gV[Bn*Hn*Ln*HDn];
__device__ float gY[Bn*Ln*En];       // [b][l][e]
__device__ float gRQ[Bn*Hn*Ln*NT];   // [bh][l][t], SCALE folded

// ---------------------------------------------------------------------------
// Tiled fp32 GEMM: C = A(MxK) @ W(NxK)^T + bias, optional head-layout store.
// BM=BN=128, BK=8, 256 threads, 8x8 per thread.
// ---------------------------------------------------------------------------
__global__ __launch_bounds__(256) void sgemm_kernel(
    const float* __restrict__ A, const float* __restrict__ W,
    const float* __restrict__ bias, float* __restrict__ Cout,
    int M, int N, int Kd, int head_layout)
{
    __shared__ float As[8][128];
    __shared__ float Bs[8][128];
    int tid = threadIdx.x;
    int lr = tid >> 1;            // 0..127
    int lc = (tid & 1) << 2;      // 0 or 4
    const float* Ap = A + (size_t)(blockIdx.y * 128 + lr) * Kd + lc;
    const float* Wp = W + (size_t)(blockIdx.x * 128 + lr) * Kd + lc;
    int tx = tid & 15, ty = tid >> 4;

    float acc[8][8];
#pragma unroll
    for (int u = 0; u < 8; u++)
#pragma unroll
        for (int v = 0; v < 8; v++) acc[u][v] = 0.f;

    for (int k0 = 0; k0 < Kd; k0 += 8) {
        float4 av = *(const float4*)(Ap + k0);
        float4 wv = *(const float4*)(Wp + k0);
        __syncthreads();
        As[lc + 0][lr] = av.x; As[lc + 1][lr] = av.y;
        As[lc + 2][lr] = av.z; As[lc + 3][lr] = av.w;
        Bs[lc + 0][lr] = wv.x; Bs[lc + 1][lr] = wv.y;
        Bs[lc + 2][lr] = wv.z; Bs[lc + 3][lr] = wv.w;
        __syncthreads();
#pragma unroll
        for (int kk = 0; kk < 8; kk++) {
            float ar[8], br[8];
            *(float4*)(ar)     = *(const float4*)&As[kk][ty * 8];
            *(float4*)(ar + 4) = *(const float4*)&As[kk][ty * 8 + 4];
            *(float4*)(br)     = *(const float4*)&Bs[kk][tx * 8];
            *(float4*)(br + 4) = *(const float4*)&Bs[kk][tx * 8 + 4];
#pragma unroll
            for (int u = 0; u < 8; u++)
#pragma unroll
                for (int v = 0; v < 8; v++)
                    acc[u][v] += ar[u] * br[v];
        }
    }

    int mbase = blockIdx.y * 128 + ty * 8;
    int nbase = blockIdx.x * 128 + tx * 8;
#pragma unroll
    for (int u = 0; u < 8; u++) {
        int m = mbase + u;
#pragma unroll
        for (int v = 0; v < 8; v += 4) {
            int n = nbase + v;
            float4 o;
            o.x = acc[u][v + 0] + bias[n + 0];
            o.y = acc[u][v + 1] + bias[n + 1];
            o.z = acc[u][v + 2] + bias[n + 2];
            o.w = acc[u][v + 3] + bias[n + 3];
            size_t off;
            if (head_layout) {
                int b = m >> 10, l = m & 1023, h = n >> 6, d = n & 63;
                off = ((size_t)b << 20) | ((size_t)h << 16) | ((size_t)l << 6) | (size_t)d;
            } else {
                off = (size_t)m * N + n;
            }
            *(float4*)(Cout + off) = o;
        }
    }
}

// ---------------------------------------------------------------------------
// RQ[row][t] = SCALE * dot(Q[row,:], rel_k[t,:]) ; row = bh*1024 + l
// block: 32 rows, 256 threads
// ---------------------------------------------------------------------------
__global__ __launch_bounds__(256) void rq_kernel(
    const float* __restrict__ Q, const float* __restrict__ relk,
    float* __restrict__ RQ)
{
    __shared__ float rk[NT][64];
    __shared__ float qs[32][64];
    int tid = threadIdx.x;
    int row0 = blockIdx.x * 32;
    for (int idx = tid; idx < NT * 64; idx += 256)
        rk[idx >> 6][idx & 63] = relk[idx];
    for (int idx = tid; idx < 32 * 64; idx += 256) {
        int r = idx >> 6, d = idx & 63;
        qs[r][d] = Q[(size_t)(row0 + r) * 64 + d];
    }
    __syncthreads();
    int r = tid >> 3;
    int g = tid & 7;
    for (int t = g; t < NT; t += 8) {
        float s = 0.f;
#pragma unroll
        for (int d = 0; d < 64; d++) s += qs[r][d] * rk[t][d];
        RQ[(size_t)(row0 + r) * NT + t] = s * SCALEF;
    }
}

// ---------------------------------------------------------------------------
// Fused flash attention with relative-position bias + rel_v bucket sums.
// grid: (16 q-tiles, 64 bh). 256 threads. 64 q-rows per block.
// ---------------------------------------------------------------------------
struct AttnSmem {
    float QsT[64][65];    // [d][i], SCALE folded
    float KsT[64][65];    // [d][j]
    float Vs[64][68];     // [j][d]
    float Ps[64][65];     // scores -> probs
    float RQs[64][NT];
    float Wb[64][NT];     // bucket weights (unnormalized)
    float relvs[NT][68];
    float mrow[64], lrow[64], alpha_s[64];
};

__global__ __launch_bounds__(256) void attn_kernel(
    const float* __restrict__ Q, const float* __restrict__ Kg,
    const float* __restrict__ Vg, const float* __restrict__ RQ,
    const float* __restrict__ relv, float* __restrict__ Y)
{
    extern __shared__ char smem_raw[];
    AttnSmem& s = *reinterpret_cast<AttnSmem*>(smem_raw);
    int tid = threadIdx.x;
    int bh = blockIdx.y;
    int i0 = blockIdx.x * 64;
    const float* Qb = Q + ((size_t)bh << 16) + (size_t)i0 * 64;
    const float* Kb = Kg + ((size_t)bh << 16);
    const float* Vb = Vg + ((size_t)bh << 16);
    const float* RQb = RQ + (size_t)(bh * 1024 + i0) * NT;

    // init loads
    {
        int r = tid >> 2;
        int dq = (tid & 3) << 4;
#pragma unroll
        for (int c = 0; c < 16; c += 4) {
            float4 v = *(const float4*)(Qb + r * 64 + dq + c);
            s.QsT[dq + c + 0][r] = v.x * SCALEF;
            s.QsT[dq + c + 1][r] = v.y * SCALEF;
            s.QsT[dq + c + 2][r] = v.z * SCALEF;
            s.QsT[dq + c + 3][r] = v.w * SCALEF;
        }
    }
    for (int idx = tid; idx < 64 * NT; idx += 256) {
        int i = idx / NT, t = idx % NT;
        s.RQs[i][t] = RQb[idx];
        s.Wb[i][t] = 0.f;
    }
    for (int idx = tid; idx < NT * 64; idx += 256)
        s.relvs[idx >> 6][idx & 63] = relv[idx];
    if (tid < 64) { s.mrow[tid] = -1e30f; s.lrow[tid] = 0.f; }

    float acc[16];
#pragma unroll
    for (int r = 0; r < 16; r++) acc[r] = 0.f;

    int tx = tid & 15, ty = tid >> 4;
    int i_acc = tid >> 2;
    int dbase = (tid & 3) << 4;

    for (int jt = 0; jt < 16; jt++) {
        int j0 = jt * 64;
        __syncthreads();
        // load K (transposed), V
        {
            int r = tid >> 2;
            int dq = (tid & 3) << 4;
#pragma unroll
            for (int c = 0; c < 16; c += 4) {
                float4 kv = *(const float4*)(Kb + (size_t)(j0 + r) * 64 + dq + c);
                s.KsT[dq + c + 0][r] = kv.x;
                s.KsT[dq + c + 1][r] = kv.y;
                s.KsT[dq + c + 2][r] = kv.z;
                s.KsT[dq + c + 3][r] = kv.w;
                float4 vv = *(const float4*)(Vb + (size_t)(j0 + r) * 64 + dq + c);
                *(float4*)&s.Vs[r][dq + c] = vv;
            }
        }
        __syncthreads();
        // S = Q K^T (+ rel bias)
        float cacc[4][4];
#pragma unroll
        for (int u = 0; u < 4; u++)
#pragma unroll
            for (int v = 0; v < 4; v++) cacc[u][v] = 0.f;
#pragma unroll
        for (int d = 0; d < 64; d++) {
            float a[4], bb[4];
#pragma unroll
            for (int u = 0; u < 4; u++) a[u] = s.QsT[d][ty * 4 + u];
#pragma unroll
            for (int v = 0; v < 4; v++) bb[v] = s.KsT[d][tx * 4 + v];
#pragma unroll
            for (int u = 0; u < 4; u++)
#pragma unroll
                for (int v = 0; v < 4; v++)
                    cacc[u][v] += a[u] * bb[v];
        }
#pragma unroll
        for (int u = 0; u < 4; u++) {
            int i = ty * 4 + u;
            int ig = i0 + i;
#pragma unroll
            for (int v = 0; v < 4; v++) {
                int j = tx * 4 + v;
                int dd = (j0 + j) - ig;
                dd = dd < -CLIPV ? -CLIPV : (dd > CLIPV ? CLIPV : dd);
                s.Ps[i][j] = cacc[u][v] + s.RQs[i][dd + CLIPV];
            }
        }
        __syncthreads();
        // per-row softmax state update (threads 0..63)
        if (tid < 64) {
            int i = tid;
            int ig = i0 + i;
            float mold = s.mrow[i];
            float mt = -1e30f;
#pragma unroll 8
            for (int j = 0; j < 64; j++) mt = fmaxf(mt, s.Ps[i][j]);
            float mnew = fmaxf(mold, mt);
            float alpha = __expf(mold - mnew);
#pragma unroll
            for (int t = 0; t < NT; t++) s.Wb[i][t] *= alpha;
            float rs = 0.f;
            for (int j = 0; j < 64; j++) {
                float p = __expf(s.Ps[i][j] - mnew);
                s.Ps[i][j] = p;
                rs += p;
                int dd = (j0 + j) - ig;
                dd = dd < -CLIPV ? -CLIPV : (dd > CLIPV ? CLIPV : dd);
                s.Wb[i][dd + CLIPV] += p;
            }
            s.lrow[i] = s.lrow[i] * alpha + rs;
            s.mrow[i] = mnew;
            s.alpha_s[i] = alpha;
        }
        __syncthreads();
        // acc = acc*alpha + P @ V
        {
            float alpha = s.alpha_s[i_acc];
#pragma unroll
            for (int r = 0; r < 16; r++) acc[r] *= alpha;
            for (int j = 0; j < 64; j++) {
                float p = s.Ps[i_acc][j];
                const float4* vp = (const float4*)&s.Vs[j][dbase];
                float4 v0 = vp[0], v1 = vp[1], v2 = vp[2], v3 = vp[3];
                acc[0]  += p * v0.x; acc[1]  += p * v0.y; acc[2]  += p * v0.z; acc[3]  += p * v0.w;
                acc[4]  += p * v1.x; acc[5]  += p * v1.y; acc[6]  += p * v1.z; acc[7]  += p * v1.w;
                acc[8]  += p * v2.x; acc[9]  += p * v2.y; acc[10] += p * v2.z; acc[11] += p * v2.w;
                acc[12] += p * v3.x; acc[13] += p * v3.y; acc[14] += p * v3.z; acc[15] += p * v3.w;
            }
        }
    }
    __syncthreads();
    // epilogue: + W @ rel_v, normalize, store
    {
        float inv = 1.f / s.lrow[i_acc];
#pragma unroll
        for (int t = 0; t < NT; t++) {
            float wv = s.Wb[i_acc][t];
            const float4* rp = (const float4*)&s.relvs[t][dbase];
            float4 r0 = rp[0], r1 = rp[1], r2 = rp[2], r3 = rp[3];
            acc[0]  += wv * r0.x; acc[1]  += wv * r0.y; acc[2]  += wv * r0.z; acc[3]  += wv * r0.w;
            acc[4]  += wv * r1.x; acc[5]  += wv * r1.y; acc[6]  += wv * r1.z; acc[7]  += wv * r1.w;
            acc[8]  += wv * r2.x; acc[9]  += wv * r2.y; acc[10] += wv * r2.z; acc[11] += wv * r2.w;
            acc[12] += wv * r3.x; acc[13] += wv * r3.y; acc[14] += wv * r3.z; acc[15] += wv * r3.w;
        }
#pragma unroll
        for (int r = 0; r < 16; r++) acc[r] *= inv;
        int b = bh >> 4, h = bh & 15;
        int l = i0 + i_acc;
        float* yp = Y + ((size_t)(b * 1024 + l)) * 1024 + h * 64 + dbase;
        *(float4*)(yp + 0)  = make_float4(acc[0],  acc[1],  acc[2],  acc[3]);
        *(float4*)(yp + 4)  = make_float4(acc[4],  acc[5],  acc[6],  acc[7]);
        *(float4*)(yp + 8)  = make_float4(acc[8],  acc[9],  acc[10], acc[11]);
        *(float4*)(yp + 12) = make_float4(acc[12], acc[13], acc[14], acc[15]);
    }
}

// ---------------------------------------------------------------------------

extern "C" void kernel_launch(void* const* d_in, const int* in_sizes, int n_in,
                              void* d_out, int out_size)
{
    const float* query = (const float*)d_in[0];
    const float* key   = (const float*)d_in[1];
    const float* value = (const float*)d_in[2];
    const float* wq = (const float*)d_in[3];
    const float* bq = (const float*)d_in[4];
    const float* wk = (const float*)d_in[5];
    const float* bk = (const float*)d_in[6];
    const float* wv = (const float*)d_in[7];
    const float* bv = (const float*)d_in[8];
    const float* wo = (const float*)d_in[9];
    const float* bo = (const float*)d_in[10];
    const float* relk = (const float*)d_in[11];
    const float* relv = (const float*)d_in[12];
    float* out = (float*)d_out;

    float *Qp, *Kp, *Vp, *Yp, *RQp;
    cudaGetSymbolAddress((void**)&Qp, gQ);
    cudaGetSymbolAddress((void**)&Kp, gK);
    cudaGetSymbolAddress((void**)&Vp, gV);
    cudaGetSymbolAddress((void**)&Yp, gY);
    cudaGetSymbolAddress((void**)&RQp, gRQ);

    dim3 gg(8, 32);  // N/128, M/128
    sgemm_kernel<<<gg, 256>>>(query, wq, bq, Qp, 4096, 1024, 1024, 1);
    sgemm_kernel<<<gg, 256>>>(key,   wk, bk, Kp, 4096, 1024, 1024, 1);
    sgemm_kernel<<<gg, 256>>>(value, wv, bv, Vp, 4096, 1024, 1024, 1);

    rq_kernel<<<2048, 256>>>(Qp, relk, RQp);

    cudaFuncSetAttribute(attn_kernel, cudaFuncAttributeMaxDynamicSharedMemorySize,
                         (int)sizeof(AttnSmem));
    attn_kernel<<<dim3(16, 64), 256, sizeof(AttnSmem)>>>(Qp, Kp, Vp, RQp, relv, Yp);

    sgemm_kernel<<<gg, 256>>>(Yp, wo, bo, out, 4096, 1024, 1024, 0);
}